// round 1
// baseline (speedup 1.0000x reference)
#include <cuda_runtime.h>
#include <math.h>

// Problem constants
#define BB   256
#define HS   512
#define G4   2048              // 4*HS
#define HEBB_PER_B (512*512)

// Scratch (device globals; no runtime allocation allowed)
__device__ float g_gates[BB * G4];     // pre-activation gates (B, 4*HS)
__device__ float g_mscalar[BB];        // tanh(h . nm_w + nm_b) per batch

__device__ __forceinline__ float sigmoidf_(float x) {
    return 1.0f / (1.0f + expf(-x));
}

// ---------------------------------------------------------------------------
// Kernel 1: gates = x @ W + h @ U + bias   (256 x 2048, K = 1024 concat)
// Tiled fp32 GEMM: BM=64, BN=64, BK=16, 256 threads, 4x4 micro-tile.
// ---------------------------------------------------------------------------
__global__ void gemm_gates_kernel(const float* __restrict__ x,
                                  const float* __restrict__ h,
                                  const float* __restrict__ W,
                                  const float* __restrict__ U,
                                  const float* __restrict__ bias) {
    __shared__ float As[16][68];   // [k][m], padded (68*4B keeps 16B alignment)
    __shared__ float Bs[16][64];   // [k][n]

    const int tid = threadIdx.x;          // 0..255
    const int m0  = blockIdx.y * 64;
    const int n0  = blockIdx.x * 64;

    const int am  = tid >> 2;             // 0..63 : A row within tile
    const int akc = (tid & 3) << 2;       // 0,4,8,12 : A k-chunk (float4)
    const int bn  = tid & 63;             // 0..63 : B col within tile
    const int bkr = tid >> 6;             // 0..3  : B k-row base

    const int mt = (tid >> 4) << 2;       // micro-tile m base (0..60)
    const int nt = (tid & 15) << 2;       // micro-tile n base (0..60)

    float acc[4][4] = {};

    for (int kt = 0; kt < 1024; kt += 16) {
        // --- load A tile (coalesced along k; each float4 stays in one half) ---
        {
            int kg = kt + akc;
            const float* asrc = (kg < 512) ? (x + (m0 + am) * 512 + kg)
                                           : (h + (m0 + am) * 512 + (kg - 512));
            float4 av = *(const float4*)asrc;
            As[akc + 0][am] = av.x;
            As[akc + 1][am] = av.y;
            As[akc + 2][am] = av.z;
            As[akc + 3][am] = av.w;
        }
        // --- load B tile (coalesced along n) ---
        #pragma unroll
        for (int j = 0; j < 4; j++) {
            int kr  = bkr + j * 4;
            int kg2 = kt + kr;
            Bs[kr][bn] = (kg2 < 512) ? W[kg2 * 2048 + n0 + bn]
                                     : U[(kg2 - 512) * 2048 + n0 + bn];
        }
        __syncthreads();

        #pragma unroll
        for (int k = 0; k < 16; k++) {
            float4 a = *(const float4*)&As[k][mt];
            float4 b = *(const float4*)&Bs[k][nt];
            acc[0][0] += a.x * b.x; acc[0][1] += a.x * b.y;
            acc[0][2] += a.x * b.z; acc[0][3] += a.x * b.w;
            acc[1][0] += a.y * b.x; acc[1][1] += a.y * b.y;
            acc[1][2] += a.y * b.z; acc[1][3] += a.y * b.w;
            acc[2][0] += a.z * b.x; acc[2][1] += a.z * b.y;
            acc[2][2] += a.z * b.z; acc[2][3] += a.z * b.w;
            acc[3][0] += a.w * b.x; acc[3][1] += a.w * b.y;
            acc[3][2] += a.w * b.z; acc[3][3] += a.w * b.w;
        }
        __syncthreads();
    }

    const int mb = m0 + mt;
    const int nb = n0 + nt;
    float4 bb = *(const float4*)&bias[nb];
    #pragma unroll
    for (int i = 0; i < 4; i++) {
        float4 o;
        o.x = acc[i][0] + bb.x;
        o.y = acc[i][1] + bb.y;
        o.z = acc[i][2] + bb.z;
        o.w = acc[i][3] + bb.w;
        *(float4*)&g_gates[(mb + i) * 2048 + nb] = o;
    }
}

// ---------------------------------------------------------------------------
// Kernel 2: m_scalar[b] = tanh( dot(h[b,:], nm_w[0,:]) + nm_b[0] )   (NM == 1)
// ---------------------------------------------------------------------------
__global__ void mscalar_kernel(const float* __restrict__ h,
                               const float* __restrict__ nm_w,
                               const float* __restrict__ nm_b) {
    const int b = blockIdx.x;
    const int t = threadIdx.x;    // 128 threads
    float s = 0.0f;
    #pragma unroll
    for (int i = t; i < 512; i += 128) s += h[b * 512 + i] * nm_w[i];
    #pragma unroll
    for (int o = 16; o > 0; o >>= 1) s += __shfl_down_sync(0xffffffff, s, o);
    __shared__ float red[4];
    if ((t & 31) == 0) red[t >> 5] = s;
    __syncthreads();
    if (t == 0)
        g_mscalar[b] = tanhf(red[0] + red[1] + red[2] + red[3] + nm_b[0]);
}

// ---------------------------------------------------------------------------
// Kernel 3: fused strip kernel. Grid (32 strips of 16 cols, 256 batches).
// Per CTA: load hebb[b, :, k0:k0+16] into SMEM (read hebb ONCE from HBM),
// reduce g_hebb, apply gates -> g/i/f/o, write h_new/c_new for owned k's,
// then update+write hebb_new strip from SMEM.
// ---------------------------------------------------------------------------
__global__ void __launch_bounds__(256)
hebb_kernel(const float* __restrict__ h_t,
            const float* __restrict__ c_t,
            const float* __restrict__ hebb,
            const float* __restrict__ alpha,
            const float* __restrict__ mt_w,
            const float* __restrict__ mt_b,
            float* __restrict__ out) {
    __shared__ float sh[512 * 16];     // 32 KB strip [i][k]
    __shared__ float hsh[512];         // h_t[b, :]
    __shared__ float red[16][17];      // partial sums [ig][ki]
    __shared__ float a_s[16];          // m_t[k] * g_t[k]

    const int b  = blockIdx.y;
    const int k0 = blockIdx.x * 16;
    const int t  = threadIdx.x;        // 256
    const float* hebb_b = hebb + (size_t)b * HEBB_PER_B;

    // --- load strip (float4, 64B segments per row) + h row ---
    {
        const int c4 = t & 3;          // float4 index within 16-col row
        const int r0 = t >> 2;         // base row 0..63
        #pragma unroll
        for (int j = 0; j < 8; j++) {
            int i = r0 + j * 64;
            float4 v = *(const float4*)(hebb_b + (size_t)i * 512 + k0 + c4 * 4);
            *(float4*)&sh[i * 16 + c4 * 4] = v;
        }
        for (int i = t; i < 512; i += 256) hsh[i] = h_t[b * 512 + i];
    }
    __syncthreads();

    // --- reduction over rows: group ig owns rows {ig, ig+16, ...} (stride 16,
    //     keeps the two row-addresses in a warp in opposite bank halves) ---
    {
        const int ki = t & 15;
        const int ig = t >> 4;
        float acc = 0.0f;
        #pragma unroll 8
        for (int s = 0; s < 32; s++) {
            int i = ig + s * 16;
            acc += hsh[i] * sh[i * 16 + ki];
        }
        red[ig][ki] = acc;
    }
    __syncthreads();

    // --- epilogue for the 16 owned k's: gates, c_new, h_new, a = m*g ---
    if (t < 16) {
        const int k = k0 + t;
        float s = 0.0f;
        #pragma unroll
        for (int g = 0; g < 16; g++) s += red[g][t];
        float ghebb = alpha[k] * s;

        const float* gb = g_gates + b * 2048;
        float zi = gb[k];
        float zf = gb[512 + k];
        float zg = gb[1024 + k];
        float zo = gb[1536 + k];

        float gt = tanhf(zg + ghebb);
        float it = sigmoidf_(zi);
        float ft = sigmoidf_(zf);
        float ot = sigmoidf_(zo);

        float cn = ft * c_t[b * 512 + k] + it * gt;
        float hn = ot * tanhf(cn);

        out[b * 512 + k]            = hn;                  // h_new
        out[BB * HS + b * 512 + k]  = cn;                  // c_new

        float mt = g_mscalar[b] * mt_w[k] + mt_b[k];
        a_s[t] = mt * gt;
    }
    __syncthreads();

    // --- update + write hebb_new strip (hebb never re-read from HBM) ---
    {
        float* outh = out + 2 * BB * HS + (size_t)b * HEBB_PER_B + k0;
        const int c4 = t & 3;
        const int r0 = t >> 2;
        float4 av = *(const float4*)&a_s[c4 * 4];
        #pragma unroll
        for (int j = 0; j < 8; j++) {
            int i = r0 + j * 64;
            float hr = hsh[i];
            float4 v = *(const float4*)&sh[i * 16 + c4 * 4];
            float4 o;
            o.x = fminf(fmaxf(v.x + hr * av.x, -2.0f), 2.0f);
            o.y = fminf(fmaxf(v.y + hr * av.y, -2.0f), 2.0f);
            o.z = fminf(fmaxf(v.z + hr * av.z, -2.0f), 2.0f);
            o.w = fminf(fmaxf(v.w + hr * av.w, -2.0f), 2.0f);
            *(float4*)(outh + (size_t)i * 512 + c4 * 4) = o;
        }
    }
}

// ---------------------------------------------------------------------------
extern "C" void kernel_launch(void* const* d_in, const int* in_sizes, int n_in,
                              void* d_out, int out_size) {
    const float* x     = (const float*)d_in[0];
    const float* h     = (const float*)d_in[1];
    const float* c     = (const float*)d_in[2];
    const float* hebb  = (const float*)d_in[3];
    const float* W     = (const float*)d_in[4];
    const float* U     = (const float*)d_in[5];
    const float* bias  = (const float*)d_in[6];
    const float* alpha = (const float*)d_in[7];
    const float* nm_w  = (const float*)d_in[8];
    const float* nm_b  = (const float*)d_in[9];
    const float* mt_w  = (const float*)d_in[10];
    const float* mt_b  = (const float*)d_in[11];
    float* out = (float*)d_out;

    (void)in_sizes; (void)n_in; (void)out_size;

    gemm_gates_kernel<<<dim3(32, 4), 256>>>(x, h, W, U, bias);
    mscalar_kernel<<<256, 128>>>(h, nm_w, nm_b);
    hebb_kernel<<<dim3(32, 256), 256>>>(h, c, hebb, alpha, mt_w, mt_b, out);
}

// round 2
// speedup vs baseline: 1.3309x; 1.3309x over previous
#include <cuda_runtime.h>
#include <math.h>

// Problem constants
#define BB   256
#define HS   512
#define G4   2048              // 4*HS
#define HEBB_PER_B (512*512)
#define NSPLIT 4               // split-K factor for the gates GEMM

// Scratch (device globals; no runtime allocation allowed)
__device__ float g_part[NSPLIT * BB * G4];   // split-K partial gates
__device__ float g_mscalar[BB];              // tanh(h . nm_w + nm_b) per batch

__device__ __forceinline__ float sigmoidf_(float x) {
    return 1.0f / (1.0f + expf(-x));
}

// ---------------------------------------------------------------------------
// Kernel 1: split-K gates GEMM.  gates = x @ W + h @ U (+ bias in split 0)
// M=256, N=2048, K=1024 (concat x|h rows vs W|U).
// Tile 64x64, BK=16, 256 threads, 4x4 micro-tile, blockIdx.z = K-split.
// Grid = 32 x 4 x 4 = 512 CTAs  (vs 128 before -> ~3.5 CTAs/SM).
// ---------------------------------------------------------------------------
__global__ void __launch_bounds__(256)
gemm_gates_kernel(const float* __restrict__ x,
                  const float* __restrict__ h,
                  const float* __restrict__ W,
                  const float* __restrict__ U,
                  const float* __restrict__ bias) {
    __shared__ float As[16][68];   // [k][m], padded
    __shared__ float Bs[16][64];   // [k][n]

    const int tid = threadIdx.x;          // 0..255
    const int m0  = blockIdx.y * 64;
    const int n0  = blockIdx.x * 64;
    const int sp  = blockIdx.z;           // K-split 0..3
    const int kbeg = sp * 256;

    const int am  = tid >> 2;             // 0..63 : A row within tile
    const int akc = (tid & 3) << 2;       // 0,4,8,12 : A k-chunk (float4)
    const int bn  = tid & 63;             // 0..63 : B col within tile
    const int bkr = tid >> 6;             // 0..3  : B k-row base

    const int mt = (tid >> 4) << 2;       // micro-tile m base
    const int nt = (tid & 15) << 2;       // micro-tile n base

    float acc[4][4] = {};

    for (int kt = kbeg; kt < kbeg + 256; kt += 16) {
        // --- load A tile (each float4 stays within one source half) ---
        {
            int kg = kt + akc;
            const float* asrc = (kg < 512) ? (x + (m0 + am) * 512 + kg)
                                           : (h + (m0 + am) * 512 + (kg - 512));
            float4 av = *(const float4*)asrc;
            As[akc + 0][am] = av.x;
            As[akc + 1][am] = av.y;
            As[akc + 2][am] = av.z;
            As[akc + 3][am] = av.w;
        }
        // --- load B tile (coalesced along n) ---
        #pragma unroll
        for (int j = 0; j < 4; j++) {
            int kr  = bkr + j * 4;
            int kg2 = kt + kr;
            Bs[kr][bn] = (kg2 < 512) ? W[kg2 * 2048 + n0 + bn]
                                     : U[(kg2 - 512) * 2048 + n0 + bn];
        }
        __syncthreads();

        #pragma unroll
        for (int k = 0; k < 16; k++) {
            float4 a = *(const float4*)&As[k][mt];
            float4 b = *(const float4*)&Bs[k][nt];
            acc[0][0] += a.x * b.x; acc[0][1] += a.x * b.y;
            acc[0][2] += a.x * b.z; acc[0][3] += a.x * b.w;
            acc[1][0] += a.y * b.x; acc[1][1] += a.y * b.y;
            acc[1][2] += a.y * b.z; acc[1][3] += a.y * b.w;
            acc[2][0] += a.z * b.x; acc[2][1] += a.z * b.y;
            acc[2][2] += a.z * b.z; acc[2][3] += a.z * b.w;
            acc[3][0] += a.w * b.x; acc[3][1] += a.w * b.y;
            acc[3][2] += a.w * b.z; acc[3][3] += a.w * b.w;
        }
        __syncthreads();
    }

    const int mb = m0 + mt;
    const int nb = n0 + nt;
    float4 bb = (sp == 0) ? *(const float4*)&bias[nb]
                          : make_float4(0.f, 0.f, 0.f, 0.f);
    float* outp = g_part + (size_t)sp * BB * G4;
    #pragma unroll
    for (int i = 0; i < 4; i++) {
        float4 o;
        o.x = acc[i][0] + bb.x;
        o.y = acc[i][1] + bb.y;
        o.z = acc[i][2] + bb.z;
        o.w = acc[i][3] + bb.w;
        *(float4*)&outp[(mb + i) * 2048 + nb] = o;
    }
}

// ---------------------------------------------------------------------------
// Kernel 2: m_scalar[b] = tanh( dot(h[b,:], nm_w[0,:]) + nm_b[0] )   (NM == 1)
// ---------------------------------------------------------------------------
__global__ void mscalar_kernel(const float* __restrict__ h,
                               const float* __restrict__ nm_w,
                               const float* __restrict__ nm_b) {
    const int b = blockIdx.x;
    const int t = threadIdx.x;    // 128 threads
    float s = 0.0f;
    #pragma unroll
    for (int i = t; i < 512; i += 128) s += h[b * 512 + i] * nm_w[i];
    #pragma unroll
    for (int o = 16; o > 0; o >>= 1) s += __shfl_down_sync(0xffffffff, s, o);
    __shared__ float red[4];
    if ((t & 31) == 0) red[t >> 5] = s;
    __syncthreads();
    if (t == 0)
        g_mscalar[b] = tanhf(red[0] + red[1] + red[2] + red[3] + nm_b[0]);
}

// ---------------------------------------------------------------------------
// Kernel 3: fused strip kernel, strip held in REGISTERS (no SMEM staging).
// Grid (32 strips of 16 cols, 256 batches), 256 threads.
// Thread t owns rows {r0, r0+64, ..., r0+448} (r0 = t>>2) x 4 cols
// (c4 = t&3 -> k = k0 + c4*4 .. +3). Quad of threads = one 64B row segment.
//   Pass 1: load 8 float4 into regs, FMA h[i]*v into acc4 (reduction).
//   Shuffle+SMEM reduce acc4 -> g_hebb[16].
//   Epilogue (16 threads): sum split-K gate partials, gates, c/h_new, a=m*g.
//   Pass 2: update regs with h[i]*a, clip, store hebb_new. hebb read ONCE.
// ---------------------------------------------------------------------------
__global__ void __launch_bounds__(256)
hebb_kernel(const float* __restrict__ h_t,
            const float* __restrict__ c_t,
            const float* __restrict__ hebb,
            const float* __restrict__ alpha,
            const float* __restrict__ mt_w,
            const float* __restrict__ mt_b,
            float* __restrict__ out) {
    __shared__ float hsh[512];         // h_t[b, :]
    __shared__ float red[8][16];       // per-warp column partials
    __shared__ float a_s[16];          // m_t[k] * g_t[k]

    const int b  = blockIdx.y;
    const int k0 = blockIdx.x * 16;
    const int t  = threadIdx.x;        // 256
    const int c4 = t & 3;              // float4 column group
    const int r0 = t >> 2;             // base row 0..63
    const int lane = t & 31;
    const int wid  = t >> 5;

    const float* hebb_b = hebb + (size_t)b * HEBB_PER_B + k0 + c4 * 4;

    // --- load h row into SMEM ---
    for (int i = t; i < 512; i += 256) hsh[i] = h_t[b * 512 + i];
    __syncthreads();

    // --- pass 1: strip -> regs, fused reduction FMA ---
    float4 v[8];
    float hr[8];
    float a0 = 0.f, a1 = 0.f, a2 = 0.f, a3 = 0.f;
    #pragma unroll
    for (int j = 0; j < 8; j++) {
        int i = r0 + j * 64;
        v[j]  = *(const float4*)(hebb_b + (size_t)i * 512);
        hr[j] = hsh[i];
    }
    #pragma unroll
    for (int j = 0; j < 8; j++) {
        a0 += hr[j] * v[j].x;
        a1 += hr[j] * v[j].y;
        a2 += hr[j] * v[j].z;
        a3 += hr[j] * v[j].w;
    }
    // warp reduce across lanes with same c4 (stride-4 lanes)
    #pragma unroll
    for (int o = 16; o >= 4; o >>= 1) {
        a0 += __shfl_down_sync(0xffffffff, a0, o);
        a1 += __shfl_down_sync(0xffffffff, a1, o);
        a2 += __shfl_down_sync(0xffffffff, a2, o);
        a3 += __shfl_down_sync(0xffffffff, a3, o);
    }
    if (lane < 4) {
        red[wid][lane * 4 + 0] = a0;
        red[wid][lane * 4 + 1] = a1;
        red[wid][lane * 4 + 2] = a2;
        red[wid][lane * 4 + 3] = a3;
    }
    __syncthreads();

    // --- epilogue for the 16 owned k's ---
    if (t < 16) {
        const int k = k0 + t;
        float s = red[0][t] + red[1][t] + red[2][t] + red[3][t]
                + red[4][t] + red[5][t] + red[6][t] + red[7][t];
        float ghebb = alpha[k] * s;

        // sum split-K gate partials
        float zi = 0.f, zf = 0.f, zg = 0.f, zo = 0.f;
        #pragma unroll
        for (int sp = 0; sp < NSPLIT; sp++) {
            const float* gb = g_part + (size_t)sp * BB * G4 + b * 2048;
            zi += gb[k];
            zf += gb[512 + k];
            zg += gb[1024 + k];
            zo += gb[1536 + k];
        }

        float gt = tanhf(zg + ghebb);
        float it = sigmoidf_(zi);
        float ft = sigmoidf_(zf);
        float ot = sigmoidf_(zo);

        float cn = ft * c_t[b * 512 + k] + it * gt;
        float hn = ot * tanhf(cn);

        out[b * 512 + k]           = hn;     // h_new
        out[BB * HS + b * 512 + k] = cn;     // c_new

        float mt = g_mscalar[b] * mt_w[k] + mt_b[k];
        a_s[t] = mt * gt;
    }
    __syncthreads();

    // --- pass 2: update regs + store hebb_new (hebb never re-read) ---
    {
        float* outh = out + 2 * BB * HS + (size_t)b * HEBB_PER_B + k0 + c4 * 4;
        float4 av = *(const float4*)&a_s[c4 * 4];
        #pragma unroll
        for (int j = 0; j < 8; j++) {
            int i = r0 + j * 64;
            float hj = hr[j];
            float4 o;
            o.x = fminf(fmaxf(v[j].x + hj * av.x, -2.0f), 2.0f);
            o.y = fminf(fmaxf(v[j].y + hj * av.y, -2.0f), 2.0f);
            o.z = fminf(fmaxf(v[j].z + hj * av.z, -2.0f), 2.0f);
            o.w = fminf(fmaxf(v[j].w + hj * av.w, -2.0f), 2.0f);
            *(float4*)(outh + (size_t)i * 512) = o;
        }
    }
}

// ---------------------------------------------------------------------------
extern "C" void kernel_launch(void* const* d_in, const int* in_sizes, int n_in,
                              void* d_out, int out_size) {
    const float* x     = (const float*)d_in[0];
    const float* h     = (const float*)d_in[1];
    const float* c     = (const float*)d_in[2];
    const float* hebb  = (const float*)d_in[3];
    const float* W     = (const float*)d_in[4];
    const float* U     = (const float*)d_in[5];
    const float* bias  = (const float*)d_in[6];
    const float* alpha = (const float*)d_in[7];
    const float* nm_w  = (const float*)d_in[8];
    const float* nm_b  = (const float*)d_in[9];
    const float* mt_w  = (const float*)d_in[10];
    const float* mt_b  = (const float*)d_in[11];
    float* out = (float*)d_out;

    (void)in_sizes; (void)n_in; (void)out_size;

    gemm_gates_kernel<<<dim3(32, 4, NSPLIT), 256>>>(x, h, W, U, bias);
    mscalar_kernel<<<256, 128>>>(h, nm_w, nm_b);
    hebb_kernel<<<dim3(32, 256), 256>>>(h, c, hebb, alpha, mt_w, mt_b, out);
}

// round 3
// speedup vs baseline: 1.3765x; 1.0343x over previous
#include <cuda_runtime.h>
#include <math.h>

// Problem constants
#define BB   256
#define HS   512
#define G4   2048              // 4*HS
#define HEBB_PER_B (512*512)
#define NSPLIT 8               // split-K factor for the gates GEMM (k=128 each)

// Scratch (device globals; no runtime allocation allowed)
__device__ float g_part[NSPLIT * BB * G4];   // split-K partial gates (16 MB)
__device__ float g_mscalar[BB];              // tanh(h . nm_w + nm_b) per batch

__device__ __forceinline__ float sigmoidf_(float x) {
    return 1.0f / (1.0f + expf(-x));
}

// ---------------------------------------------------------------------------
// Kernel 1: split-K gates GEMM.  gates = x @ W + h @ U (+ bias in split 0)
// M=256, N=2048, K=1024 (concat x|h vs W|U). Each split (128 k) lies entirely
// in one half, so source pointers are hoisted.
// Tile 64x128, BK=16, 256 threads, 4x8 micro-tile. Grid = 16 x 4 x 8 = 512.
// ---------------------------------------------------------------------------
__global__ void __launch_bounds__(256)
gemm_gates_kernel(const float* __restrict__ x,
                  const float* __restrict__ h,
                  const float* __restrict__ W,
                  const float* __restrict__ U,
                  const float* __restrict__ bias) {
    __shared__ float As[16][68];    // [k][m], padded
    __shared__ float Bs[16][128];   // [k][n]

    const int tid = threadIdx.x;          // 0..255
    const int n0  = blockIdx.x * 128;
    const int m0  = blockIdx.y * 64;
    const int sp  = blockIdx.z;           // K-split 0..7

    const float* Amat = (sp < 4) ? x : h;      // each split fully in one half
    const float* Bmat = (sp < 4) ? W : U;
    const int kb = (sp & 3) * 128;

    // A-load map: 64 rows x 16 k = 1 float4/thread
    const int am  = tid >> 2;             // 0..63
    const int ak4 = (tid & 3) << 2;       // k offset 0,4,8,12
    // B-load map: 16 rows x 128 cols = 2 float4/thread
    const int bk  = tid >> 4;             // 0..15 row
    const int bn4 = (tid & 15) << 2;      // col base (plus +64 second chunk)

    // micro-tile: 4 rows x 8 cols
    const int mt = (tid >> 4) << 2;       // 0..60
    const int nt = (tid & 15) << 3;       // 0..120

    float acc[4][8] = {};

    for (int kt = kb; kt < kb + 128; kt += 16) {
        // --- A tile ---
        {
            float4 av = *(const float4*)(Amat + (m0 + am) * 512 + kt + ak4);
            As[ak4 + 0][am] = av.x;
            As[ak4 + 1][am] = av.y;
            As[ak4 + 2][am] = av.z;
            As[ak4 + 3][am] = av.w;
        }
        // --- B tile (coalesced along n) ---
        {
            const float* bsrc = Bmat + (size_t)(kt + bk) * 2048 + n0 + bn4;
            *(float4*)&Bs[bk][bn4]      = *(const float4*)(bsrc);
            *(float4*)&Bs[bk][bn4 + 64] = *(const float4*)(bsrc + 64);
        }
        __syncthreads();

        #pragma unroll
        for (int k = 0; k < 16; k++) {
            float4 a  = *(const float4*)&As[k][mt];
            float4 b0 = *(const float4*)&Bs[k][nt];
            float4 b1 = *(const float4*)&Bs[k][nt + 4];
            acc[0][0] += a.x * b0.x; acc[0][1] += a.x * b0.y;
            acc[0][2] += a.x * b0.z; acc[0][3] += a.x * b0.w;
            acc[0][4] += a.x * b1.x; acc[0][5] += a.x * b1.y;
            acc[0][6] += a.x * b1.z; acc[0][7] += a.x * b1.w;
            acc[1][0] += a.y * b0.x; acc[1][1] += a.y * b0.y;
            acc[1][2] += a.y * b0.z; acc[1][3] += a.y * b0.w;
            acc[1][4] += a.y * b1.x; acc[1][5] += a.y * b1.y;
            acc[1][6] += a.y * b1.z; acc[1][7] += a.y * b1.w;
            acc[2][0] += a.z * b0.x; acc[2][1] += a.z * b0.y;
            acc[2][2] += a.z * b0.z; acc[2][3] += a.z * b0.w;
            acc[2][4] += a.z * b1.x; acc[2][5] += a.z * b1.y;
            acc[2][6] += a.z * b1.z; acc[2][7] += a.z * b1.w;
            acc[3][0] += a.w * b0.x; acc[3][1] += a.w * b0.y;
            acc[3][2] += a.w * b0.z; acc[3][3] += a.w * b0.w;
            acc[3][4] += a.w * b1.x; acc[3][5] += a.w * b1.y;
            acc[3][6] += a.w * b1.z; acc[3][7] += a.w * b1.w;
        }
        __syncthreads();
    }

    const int mb = m0 + mt;
    const int nb = n0 + nt;
    float* outp = g_part + (size_t)sp * BB * G4;
    #pragma unroll
    for (int i = 0; i < 4; i++) {
        float4 o0 = make_float4(acc[i][0], acc[i][1], acc[i][2], acc[i][3]);
        float4 o1 = make_float4(acc[i][4], acc[i][5], acc[i][6], acc[i][7]);
        if (sp == 0) {
            float4 b0 = *(const float4*)&bias[nb];
            float4 b1 = *(const float4*)&bias[nb + 4];
            o0.x += b0.x; o0.y += b0.y; o0.z += b0.z; o0.w += b0.w;
            o1.x += b1.x; o1.y += b1.y; o1.z += b1.z; o1.w += b1.w;
        }
        *(float4*)&outp[(mb + i) * 2048 + nb]     = o0;
        *(float4*)&outp[(mb + i) * 2048 + nb + 4] = o1;
    }
}

// ---------------------------------------------------------------------------
// Kernel 2: m_scalar[b] = tanh( dot(h[b,:], nm_w[0,:]) + nm_b[0] )   (NM == 1)
// ---------------------------------------------------------------------------
__global__ void mscalar_kernel(const float* __restrict__ h,
                               const float* __restrict__ nm_w,
                               const float* __restrict__ nm_b) {
    const int b = blockIdx.x;
    const int t = threadIdx.x;    // 128 threads
    float s = 0.0f;
    #pragma unroll
    for (int i = t; i < 512; i += 128) s += h[b * 512 + i] * nm_w[i];
    #pragma unroll
    for (int o = 16; o > 0; o >>= 1) s += __shfl_down_sync(0xffffffff, s, o);
    __shared__ float red[4];
    if ((t & 31) == 0) red[t >> 5] = s;
    __syncthreads();
    if (t == 0)
        g_mscalar[b] = tanhf(red[0] + red[1] + red[2] + red[3] + nm_b[0]);
}

// ---------------------------------------------------------------------------
// Kernel 3: fused strip kernel, strip held in REGISTERS.
// Grid (32 strips of 16 cols, 256 batches), 256 threads.
// Thread t owns rows {r0, r0+64, ..., r0+448} (r0=t>>2) x 4 cols (c4=t&3).
//   Front: issue strip LDG.128 x8, h LDG x8 (quad-broadcast), and gate
//          partial prefetch (threads 0..127 -> gsm) all before any wait.
//   Reduce: FMA + warp shuffles -> red[8][16].
//   Epilogue (16 threads, pure ALU/LDS): sum partials, gates, c/h_new, a=m*g.
//   Store: update regs with h[i]*a, clip, write hebb_new. hebb read ONCE.
// ---------------------------------------------------------------------------
__global__ void __launch_bounds__(256)
hebb_kernel(const float* __restrict__ h_t,
            const float* __restrict__ c_t,
            const float* __restrict__ hebb,
            const float* __restrict__ alpha,
            const float* __restrict__ mt_w,
            const float* __restrict__ mt_b,
            float* __restrict__ out) {
    __shared__ float red[8][16];       // per-warp column partials
    __shared__ float gsm[NSPLIT][4][16]; // gate partials [sp][gate][k]
    __shared__ float a_s[16];          // m_t[k] * g_t[k]

    const int b  = blockIdx.y;
    const int k0 = blockIdx.x * 16;
    const int t  = threadIdx.x;        // 256
    const int c4 = t & 3;              // float4 column group
    const int r0 = t >> 2;             // base row 0..63
    const int lane = t & 31;
    const int wid  = t >> 5;

    const float* hebb_b = hebb + (size_t)b * HEBB_PER_B + k0 + c4 * 4;
    const float* hrow   = h_t + b * 512;

    // --- front: all global loads issued before any dependency stall ---
    float4 v[8];
    float hr[8];
    #pragma unroll
    for (int j = 0; j < 8; j++)
        v[j] = *(const float4*)(hebb_b + (size_t)(r0 + j * 64) * 512);
    #pragma unroll
    for (int j = 0; j < 8; j++)
        hr[j] = __ldg(hrow + r0 + j * 64);
    if (t < 128) {
        const int ki = t & 15;
        const int sp = t >> 4;
        const float* gb = g_part + (size_t)sp * BB * G4 + b * 2048 + k0 + ki;
        gsm[sp][0][ki] = gb[0];
        gsm[sp][1][ki] = gb[512];
        gsm[sp][2][ki] = gb[1024];
        gsm[sp][3][ki] = gb[1536];
    }

    // --- reduction: acc over this thread's 8 rows ---
    float a0 = 0.f, a1 = 0.f, a2 = 0.f, a3 = 0.f;
    #pragma unroll
    for (int j = 0; j < 8; j++) {
        a0 += hr[j] * v[j].x;
        a1 += hr[j] * v[j].y;
        a2 += hr[j] * v[j].z;
        a3 += hr[j] * v[j].w;
    }
    // warp reduce across lanes with same c4 (stride-4 lanes)
    #pragma unroll
    for (int o = 16; o >= 4; o >>= 1) {
        a0 += __shfl_down_sync(0xffffffff, a0, o);
        a1 += __shfl_down_sync(0xffffffff, a1, o);
        a2 += __shfl_down_sync(0xffffffff, a2, o);
        a3 += __shfl_down_sync(0xffffffff, a3, o);
    }
    if (lane < 4) {
        red[wid][lane * 4 + 0] = a0;
        red[wid][lane * 4 + 1] = a1;
        red[wid][lane * 4 + 2] = a2;
        red[wid][lane * 4 + 3] = a3;
    }
    __syncthreads();

    // --- epilogue for the 16 owned k's (ALU + SMEM only) ---
    if (t < 16) {
        const int k = k0 + t;
        float s = red[0][t] + red[1][t] + red[2][t] + red[3][t]
                + red[4][t] + red[5][t] + red[6][t] + red[7][t];
        float ghebb = alpha[k] * s;

        float zi = 0.f, zf = 0.f, zg = 0.f, zo = 0.f;
        #pragma unroll
        for (int sp = 0; sp < NSPLIT; sp++) {
            zi += gsm[sp][0][t];
            zf += gsm[sp][1][t];
            zg += gsm[sp][2][t];
            zo += gsm[sp][3][t];
        }

        float gt = tanhf(zg + ghebb);
        float it = sigmoidf_(zi);
        float ft = sigmoidf_(zf);
        float ot = sigmoidf_(zo);

        float cn = ft * c_t[b * 512 + k] + it * gt;
        float hn = ot * tanhf(cn);

        out[b * 512 + k]           = hn;     // h_new
        out[BB * HS + b * 512 + k] = cn;     // c_new

        float mt = g_mscalar[b] * mt_w[k] + mt_b[k];
        a_s[t] = mt * gt;
    }
    __syncthreads();

    // --- store: update regs + write hebb_new (hebb never re-read) ---
    {
        float* outh = out + 2 * BB * HS + (size_t)b * HEBB_PER_B + k0 + c4 * 4;
        float4 av = *(const float4*)&a_s[c4 * 4];
        #pragma unroll
        for (int j = 0; j < 8; j++) {
            int i = r0 + j * 64;
            float hj = hr[j];
            float4 o;
            o.x = fminf(fmaxf(v[j].x + hj * av.x, -2.0f), 2.0f);
            o.y = fminf(fmaxf(v[j].y + hj * av.y, -2.0f), 2.0f);
            o.z = fminf(fmaxf(v[j].z + hj * av.z, -2.0f), 2.0f);
            o.w = fminf(fmaxf(v[j].w + hj * av.w, -2.0f), 2.0f);
            *(float4*)(outh + (size_t)i * 512) = o;
        }
    }
}

// ---------------------------------------------------------------------------
extern "C" void kernel_launch(void* const* d_in, const int* in_sizes, int n_in,
                              void* d_out, int out_size) {
    const float* x     = (const float*)d_in[0];
    const float* h     = (const float*)d_in[1];
    const float* c     = (const float*)d_in[2];
    const float* hebb  = (const float*)d_in[3];
    const float* W     = (const float*)d_in[4];
    const float* U     = (const float*)d_in[5];
    const float* bias  = (const float*)d_in[6];
    const float* alpha = (const float*)d_in[7];
    const float* nm_w  = (const float*)d_in[8];
    const float* nm_b  = (const float*)d_in[9];
    const float* mt_w  = (const float*)d_in[10];
    const float* mt_b  = (const float*)d_in[11];
    float* out = (float*)d_out;

    (void)in_sizes; (void)n_in; (void)out_size;

    gemm_gates_kernel<<<dim3(16, 4, NSPLIT), 256>>>(x, h, W, U, bias);
    mscalar_kernel<<<256, 128>>>(h, nm_w, nm_b);
    hebb_kernel<<<dim3(32, 256), 256>>>(h, c, hebb, alpha, mt_w, mt_b, out);
}

// round 4
// speedup vs baseline: 1.5866x; 1.1526x over previous
#include <cuda_runtime.h>
#include <math.h>

// Problem constants
#define BB   256
#define HS   512
#define G4   2048              // 4*HS
#define HEBB_PER_B (512*512)
#define NSPLIT 4               // split-K factor for the gates GEMM (k=256 each)

// Scratch (device globals; no runtime allocation allowed)
__device__ float g_part[NSPLIT * BB * G4];   // split-K partial gates (8 MB)
__device__ float g_mscalar[BB];              // tanh(h . nm_w + nm_b) per batch

__device__ __forceinline__ float sigmoidf_(float x) {
    return 1.0f / (1.0f + expf(-x));
}

// ---------------------------------------------------------------------------
// Kernel 1: split-K gates GEMM, double-buffered SMEM.
// gates = x @ W + h @ U (+ bias in split 0)
// M=256, N=2048, K=1024 (concat x|h vs W|U). Each 256-wide split lies fully
// in one half -> source pointers hoisted.
// Tile 64x64, BK=16, 256 threads, 4x4 micro-tile. Grid = 32 x 4 x 4 = 512.
// One __syncthreads per BK-tile; LDG prefetch overlaps FFMA compute.
// ---------------------------------------------------------------------------
__global__ void __launch_bounds__(256)
gemm_gates_kernel(const float* __restrict__ x,
                  const float* __restrict__ h,
                  const float* __restrict__ W,
                  const float* __restrict__ U,
                  const float* __restrict__ bias) {
    __shared__ float As[2][16][68];   // [buf][k][m], padded
    __shared__ float Bs[2][16][64];   // [buf][k][n]

    const int tid = threadIdx.x;          // 0..255
    const int n0  = blockIdx.x * 64;
    const int m0  = blockIdx.y * 64;
    const int sp  = blockIdx.z;           // K-split 0..3

    const float* Amat = (sp < 2) ? x : h;
    const float* Bmat = (sp < 2) ? W : U;
    const int kb = (sp & 1) * 256;

    // A-load map: 64 rows x 16 k = 1 float4/thread
    const int am  = tid >> 2;             // 0..63
    const int ak4 = (tid & 3) << 2;       // k offset 0,4,8,12
    // B-load map: 16 rows x 64 cols = 4 floats/thread
    const int bkr = tid >> 6;             // 0..3 row base
    const int bn  = tid & 63;             // col

    // micro-tile: 4x4
    const int mt = (tid >> 4) << 2;
    const int nt = (tid & 15) << 2;

    const float* aptr = Amat + (m0 + am) * 512 + kb + ak4;
    const float* bptr = Bmat + (size_t)(kb + bkr) * 2048 + n0 + bn;

    float acc[4][4] = {};

    // initial prefetch (tile 0)
    float4 aR = *(const float4*)aptr;
    float  bR0 = bptr[0];
    float  bR1 = bptr[4 * 2048];
    float  bR2 = bptr[8 * 2048];
    float  bR3 = bptr[12 * 2048];
    aptr += 16;
    bptr += 16 * 2048;

    int cur = 0;
    #pragma unroll 1
    for (int it = 0; it < 16; ++it) {
        // STS current tile
        As[cur][ak4 + 0][am] = aR.x;
        As[cur][ak4 + 1][am] = aR.y;
        As[cur][ak4 + 2][am] = aR.z;
        As[cur][ak4 + 3][am] = aR.w;
        Bs[cur][bkr + 0][bn]  = bR0;
        Bs[cur][bkr + 4][bn]  = bR1;
        Bs[cur][bkr + 8][bn]  = bR2;
        Bs[cur][bkr + 12][bn] = bR3;
        __syncthreads();

        // prefetch next tile (overlaps compute)
        if (it < 15) {
            aR  = *(const float4*)aptr;
            bR0 = bptr[0];
            bR1 = bptr[4 * 2048];
            bR2 = bptr[8 * 2048];
            bR3 = bptr[12 * 2048];
            aptr += 16;
            bptr += 16 * 2048;
        }

        #pragma unroll
        for (int k = 0; k < 16; k++) {
            float4 a = *(const float4*)&As[cur][k][mt];
            float4 b = *(const float4*)&Bs[cur][k][nt];
            acc[0][0] += a.x * b.x; acc[0][1] += a.x * b.y;
            acc[0][2] += a.x * b.z; acc[0][3] += a.x * b.w;
            acc[1][0] += a.y * b.x; acc[1][1] += a.y * b.y;
            acc[1][2] += a.y * b.z; acc[1][3] += a.y * b.w;
            acc[2][0] += a.z * b.x; acc[2][1] += a.z * b.y;
            acc[2][2] += a.z * b.z; acc[2][3] += a.z * b.w;
            acc[3][0] += a.w * b.x; acc[3][1] += a.w * b.y;
            acc[3][2] += a.w * b.z; acc[3][3] += a.w * b.w;
        }
        cur ^= 1;
    }

    const int mb = m0 + mt;
    const int nb = n0 + nt;
    float4 bb = (sp == 0) ? *(const float4*)&bias[nb]
                          : make_float4(0.f, 0.f, 0.f, 0.f);
    float* outp = g_part + (size_t)sp * BB * G4;
    #pragma unroll
    for (int i = 0; i < 4; i++) {
        float4 o;
        o.x = acc[i][0] + bb.x;
        o.y = acc[i][1] + bb.y;
        o.z = acc[i][2] + bb.z;
        o.w = acc[i][3] + bb.w;
        *(float4*)&outp[(mb + i) * 2048 + nb] = o;
    }
}

// ---------------------------------------------------------------------------
// Kernel 2: m_scalar[b] = tanh( dot(h[b,:], nm_w[0,:]) + nm_b[0] )   (NM == 1)
// ---------------------------------------------------------------------------
__global__ void mscalar_kernel(const float* __restrict__ h,
                               const float* __restrict__ nm_w,
                               const float* __restrict__ nm_b) {
    const int b = blockIdx.x;
    const int t = threadIdx.x;    // 128 threads
    float s = 0.0f;
    #pragma unroll
    for (int i = t; i < 512; i += 128) s += h[b * 512 + i] * nm_w[i];
    #pragma unroll
    for (int o = 16; o > 0; o >>= 1) s += __shfl_down_sync(0xffffffff, s, o);
    __shared__ float red[4];
    if ((t & 31) == 0) red[t >> 5] = s;
    __syncthreads();
    if (t == 0)
        g_mscalar[b] = tanhf(red[0] + red[1] + red[2] + red[3] + nm_b[0]);
}

// ---------------------------------------------------------------------------
// Kernel 3: fused strip kernel, strip held in REGISTERS, streaming hints.
// Grid (32 strips of 16 cols, 256 batches), 256 threads.
// Thread t owns rows {r0, r0+64, ..., r0+448} (r0=t>>2) x 4 cols (c4=t&3).
// hebb is read ONCE (ldcs) and hebb_new written once (stcs) — zero reuse.
// ---------------------------------------------------------------------------
__global__ void __launch_bounds__(256)
hebb_kernel(const float* __restrict__ h_t,
            const float* __restrict__ c_t,
            const float* __restrict__ hebb,
            const float* __restrict__ alpha,
            const float* __restrict__ mt_w,
            const float* __restrict__ mt_b,
            float* __restrict__ out) {
    __shared__ float red[8][16];         // per-warp column partials
    __shared__ float gsm[NSPLIT][4][16]; // gate partials [sp][gate][k]
    __shared__ float a_s[16];            // m_t[k] * g_t[k]

    const int b  = blockIdx.y;
    const int k0 = blockIdx.x * 16;
    const int t  = threadIdx.x;        // 256
    const int c4 = t & 3;              // float4 column group
    const int r0 = t >> 2;             // base row 0..63
    const int lane = t & 31;
    const int wid  = t >> 5;

    const float* hebb_b = hebb + (size_t)b * HEBB_PER_B + k0 + c4 * 4;
    const float* hrow   = h_t + b * 512;

    // --- front: all global loads issued before any dependency stall ---
    float4 v[8];
    float hr[8];
    #pragma unroll
    for (int j = 0; j < 8; j++)
        v[j] = __ldcs((const float4*)(hebb_b + (size_t)(r0 + j * 64) * 512));
    #pragma unroll
    for (int j = 0; j < 8; j++)
        hr[j] = __ldg(hrow + r0 + j * 64);
    if (t < 16 * NSPLIT) {
        const int ki = t & 15;
        const int sp = t >> 4;
        const float* gb = g_part + (size_t)sp * BB * G4 + b * 2048 + k0 + ki;
        gsm[sp][0][ki] = gb[0];
        gsm[sp][1][ki] = gb[512];
        gsm[sp][2][ki] = gb[1024];
        gsm[sp][3][ki] = gb[1536];
    }

    // --- reduction: acc over this thread's 8 rows ---
    float a0 = 0.f, a1 = 0.f, a2 = 0.f, a3 = 0.f;
    #pragma unroll
    for (int j = 0; j < 8; j++) {
        a0 += hr[j] * v[j].x;
        a1 += hr[j] * v[j].y;
        a2 += hr[j] * v[j].z;
        a3 += hr[j] * v[j].w;
    }
    // warp reduce across lanes with same c4 (stride-4 lanes)
    #pragma unroll
    for (int o = 16; o >= 4; o >>= 1) {
        a0 += __shfl_down_sync(0xffffffff, a0, o);
        a1 += __shfl_down_sync(0xffffffff, a1, o);
        a2 += __shfl_down_sync(0xffffffff, a2, o);
        a3 += __shfl_down_sync(0xffffffff, a3, o);
    }
    if (lane < 4) {
        red[wid][lane * 4 + 0] = a0;
        red[wid][lane * 4 + 1] = a1;
        red[wid][lane * 4 + 2] = a2;
        red[wid][lane * 4 + 3] = a3;
    }
    __syncthreads();

    // --- epilogue for the 16 owned k's (ALU + SMEM only) ---
    if (t < 16) {
        const int k = k0 + t;
        float s = red[0][t] + red[1][t] + red[2][t] + red[3][t]
                + red[4][t] + red[5][t] + red[6][t] + red[7][t];
        float ghebb = alpha[k] * s;

        float zi = 0.f, zf = 0.f, zg = 0.f, zo = 0.f;
        #pragma unroll
        for (int sp = 0; sp < NSPLIT; sp++) {
            zi += gsm[sp][0][t];
            zf += gsm[sp][1][t];
            zg += gsm[sp][2][t];
            zo += gsm[sp][3][t];
        }

        float gt = tanhf(zg + ghebb);
        float it = sigmoidf_(zi);
        float ft = sigmoidf_(zf);
        float ot = sigmoidf_(zo);

        float cn = ft * c_t[b * 512 + k] + it * gt;
        float hn = ot * tanhf(cn);

        out[b * 512 + k]           = hn;     // h_new
        out[BB * HS + b * 512 + k] = cn;     // c_new

        float mt = g_mscalar[b] * mt_w[k] + mt_b[k];
        a_s[t] = mt * gt;
    }
    __syncthreads();

    // --- store: update regs + write hebb_new (streaming stores) ---
    {
        float* outh = out + 2 * BB * HS + (size_t)b * HEBB_PER_B + k0 + c4 * 4;
        float4 av = *(const float4*)&a_s[c4 * 4];
        #pragma unroll
        for (int j = 0; j < 8; j++) {
            int i = r0 + j * 64;
            float hj = hr[j];
            float4 o;
            o.x = fminf(fmaxf(v[j].x + hj * av.x, -2.0f), 2.0f);
            o.y = fminf(fmaxf(v[j].y + hj * av.y, -2.0f), 2.0f);
            o.z = fminf(fmaxf(v[j].z + hj * av.z, -2.0f), 2.0f);
            o.w = fminf(fmaxf(v[j].w + hj * av.w, -2.0f), 2.0f);
            __stcs((float4*)(outh + (size_t)i * 512), o);
        }
    }
}

// ---------------------------------------------------------------------------
extern "C" void kernel_launch(void* const* d_in, const int* in_sizes, int n_in,
                              void* d_out, int out_size) {
    const float* x     = (const float*)d_in[0];
    const float* h     = (const float*)d_in[1];
    const float* c     = (const float*)d_in[2];
    const float* hebb  = (const float*)d_in[3];
    const float* W     = (const float*)d_in[4];
    const float* U     = (const float*)d_in[5];
    const float* bias  = (const float*)d_in[6];
    const float* alpha = (const float*)d_in[7];
    const float* nm_w  = (const float*)d_in[8];
    const float* nm_b  = (const float*)d_in[9];
    const float* mt_w  = (const float*)d_in[10];
    const float* mt_b  = (const float*)d_in[11];
    float* out = (float*)d_out;

    (void)in_sizes; (void)n_in; (void)out_size;

    gemm_gates_kernel<<<dim3(32, 4, NSPLIT), 256>>>(x, h, W, U, bias);
    mscalar_kernel<<<256, 128>>>(h, nm_w, nm_b);
    hebb_kernel<<<dim3(32, 256), 256>>>(h, c, hebb, alpha, mt_w, mt_b, out);
}

// round 5
// speedup vs baseline: 1.8008x; 1.1350x over previous
#include <cuda_runtime.h>
#include <math.h>
#include <stdint.h>

// Problem constants
#define BB   256
#define HS   512
#define G4   2048              // 4*HS
#define HEBB_PER_B (512*512)
#define NSPLIT 4               // split-K factor for the gates GEMM (k=256 each)

// Scratch (device globals; no runtime allocation allowed)
__device__ float g_part[NSPLIT * BB * G4];   // split-K partial gates (8 MB)
__device__ float g_mscalar[BB];              // tanh(h . nm_w + nm_b) per batch

__device__ __forceinline__ float sigmoidf_(float x) {
    return 1.0f / (1.0f + expf(-x));
}

__device__ __forceinline__ uint32_t f2tf32(float f) {
    uint32_t r;
    asm("cvt.rna.tf32.f32 %0, %1;" : "=r"(r) : "f"(f));
    return r;
}

__device__ __forceinline__ void mma_tf32(float& c0, float& c1, float& c2, float& c3,
                                         uint32_t a0, uint32_t a1, uint32_t a2, uint32_t a3,
                                         uint32_t b0, uint32_t b1) {
    asm volatile(
        "mma.sync.aligned.m16n8k8.row.col.f32.tf32.tf32.f32 "
        "{%0,%1,%2,%3}, {%4,%5,%6,%7}, {%8,%9}, {%0,%1,%2,%3};"
        : "+f"(c0), "+f"(c1), "+f"(c2), "+f"(c3)
        : "r"(a0), "r"(a1), "r"(a2), "r"(a3), "r"(b0), "r"(b1));
}

// ---------------------------------------------------------------------------
// Kernel 1: split-K gates GEMM on TENSOR CORES (tf32 mma.sync m16n8k8).
// gates = x @ W + h @ U (+ bias in split 0).  M=256, N=2048, K=1024.
// CTA: 64x64 tile, 256 thr = 8 warps (4 m x 2 n), warp tile 16x32.
// k-chunk 32, double-buffered SMEM, one barrier per chunk.
// A smem [k][m] rotated (m+8k)&63 -> conflict-free frag loads.
// B smem [k][n] pad 72          -> conflict-free frag loads.
// Grid = 32 x 4 x 4 = 512 CTAs.
// ---------------------------------------------------------------------------
__global__ void __launch_bounds__(256)
gemm_gates_kernel(const float* __restrict__ x,
                  const float* __restrict__ h,
                  const float* __restrict__ W,
                  const float* __restrict__ U,
                  const float* __restrict__ bias) {
    __shared__ uint32_t As[2][32][64];   // [buf][k][m rotated]
    __shared__ uint32_t Bs[2][32][72];   // [buf][k][n], pad 72

    const int tid  = threadIdx.x;        // 0..255
    const int lane = tid & 31;
    const int warp = tid >> 5;
    const int gid  = lane >> 2;          // 0..7
    const int tig  = lane & 3;           // 0..3
    const int wm   = (warp & 3) << 4;    // warp m offset 0..48
    const int wn   = (warp >> 2) << 5;   // warp n offset 0 or 32

    const int n0 = blockIdx.x * 64;
    const int m0 = blockIdx.y * 64;
    const int sp = blockIdx.z;           // K-split 0..3

    const float* Amat = (sp < 2) ? x : h;
    const float* Bmat = (sp < 2) ? W : U;
    const int kb = (sp & 1) * 256;

    // global load maps
    const int arow = tid >> 2;           // 0..63
    const int akc4 = (tid & 3) << 2;     // 0,4,8,12 (second chunk +16)
    const int bkr  = tid >> 3;           // 0..31
    const int bnc4 = (tid & 7) << 2;     // 0..28    (second chunk +32)

    const float* aptr = Amat + (m0 + arow) * 512 + kb + akc4;
    const float* bptr = Bmat + (size_t)(kb + bkr) * 2048 + n0 + bnc4;

    float acc[4][4] = {};                // [n-tile][reg]

    // prefetch chunk 0
    float4 aV0 = *(const float4*)(aptr);
    float4 aV1 = *(const float4*)(aptr + 16);
    float4 bV0 = *(const float4*)(bptr);
    float4 bV1 = *(const float4*)(bptr + 32);
    aptr += 32;
    bptr += (size_t)32 * 2048;

    #pragma unroll 1
    for (int chunk = 0; chunk < 8; ++chunk) {
        const int cur = chunk & 1;

        // --- STS A (transpose + rotate + tf32 cvt) ---
        {
            const float av0[4] = {aV0.x, aV0.y, aV0.z, aV0.w};
            const float av1[4] = {aV1.x, aV1.y, aV1.z, aV1.w};
            #pragma unroll
            for (int j = 0; j < 4; j++) {
                int k1 = akc4 + j;
                As[cur][k1][(arow + 8 * k1) & 63]            = f2tf32(av0[j]);
                As[cur][k1 + 16][(arow + 8 * (k1 + 16)) & 63] = f2tf32(av1[j]);
            }
        }
        // --- STS B (tf32 cvt, float4) ---
        {
            uint4 p0 = make_uint4(f2tf32(bV0.x), f2tf32(bV0.y), f2tf32(bV0.z), f2tf32(bV0.w));
            uint4 p1 = make_uint4(f2tf32(bV1.x), f2tf32(bV1.y), f2tf32(bV1.z), f2tf32(bV1.w));
            *(uint4*)&Bs[cur][bkr][bnc4]      = p0;
            *(uint4*)&Bs[cur][bkr][bnc4 + 32] = p1;
        }
        __syncthreads();

        // prefetch next chunk (overlaps mma)
        if (chunk < 7) {
            aV0 = *(const float4*)(aptr);
            aV1 = *(const float4*)(aptr + 16);
            bV0 = *(const float4*)(bptr);
            bV1 = *(const float4*)(bptr + 32);
            aptr += 32;
            bptr += (size_t)32 * 2048;
        }

        // --- compute: 4 k-steps of 8 ---
        #pragma unroll
        for (int ks = 0; ks < 32; ks += 8) {
            const int kA = ks + tig;
            const int kB = ks + tig + 4;
            uint32_t a0 = As[cur][kA][(wm + gid +     8 * kA) & 63];
            uint32_t a1 = As[cur][kA][(wm + gid + 8 + 8 * kA) & 63];
            uint32_t a2 = As[cur][kB][(wm + gid +     8 * kB) & 63];
            uint32_t a3 = As[cur][kB][(wm + gid + 8 + 8 * kB) & 63];
            #pragma unroll
            for (int nt = 0; nt < 4; nt++) {
                uint32_t b0 = Bs[cur][kA][wn + nt * 8 + gid];
                uint32_t b1 = Bs[cur][kB][wn + nt * 8 + gid];
                mma_tf32(acc[nt][0], acc[nt][1], acc[nt][2], acc[nt][3],
                         a0, a1, a2, a3, b0, b1);
            }
        }
    }

    // --- epilogue: write 64x64 accum to g_part[sp] (+ bias on split 0) ---
    float* outp = g_part + (size_t)sp * BB * G4;
    const int row0 = m0 + wm + gid;
    #pragma unroll
    for (int nt = 0; nt < 4; nt++) {
        const int col = n0 + wn + nt * 8 + 2 * tig;
        float b0 = 0.f, b1 = 0.f;
        if (sp == 0) { b0 = bias[col]; b1 = bias[col + 1]; }
        float2 d0 = make_float2(acc[nt][0] + b0, acc[nt][1] + b1);
        float2 d1 = make_float2(acc[nt][2] + b0, acc[nt][3] + b1);
        *(float2*)&outp[(size_t)row0 * 2048 + col]       = d0;
        *(float2*)&outp[(size_t)(row0 + 8) * 2048 + col] = d1;
    }
}

// ---------------------------------------------------------------------------
// Kernel 2: m_scalar[b] = tanh( dot(h[b,:], nm_w[0,:]) + nm_b[0] )   (NM == 1)
// ---------------------------------------------------------------------------
__global__ void mscalar_kernel(const float* __restrict__ h,
                               const float* __restrict__ nm_w,
                               const float* __restrict__ nm_b) {
    const int b = blockIdx.x;
    const int t = threadIdx.x;    // 128 threads
    float s = 0.0f;
    #pragma unroll
    for (int i = t; i < 512; i += 128) s += h[b * 512 + i] * nm_w[i];
    #pragma unroll
    for (int o = 16; o > 0; o >>= 1) s += __shfl_down_sync(0xffffffff, s, o);
    __shared__ float red[4];
    if ((t & 31) == 0) red[t >> 5] = s;
    __syncthreads();
    if (t == 0)
        g_mscalar[b] = tanhf(red[0] + red[1] + red[2] + red[3] + nm_b[0]);
}

// ---------------------------------------------------------------------------
// Kernel 3: fused strip kernel, strip held in REGISTERS, streaming hints.
// Grid (32 strips of 16 cols, 256 batches), 256 threads.
// hebb is read ONCE (ldcs) and hebb_new written once (stcs).
// ---------------------------------------------------------------------------
__global__ void __launch_bounds__(256)
hebb_kernel(const float* __restrict__ h_t,
            const float* __restrict__ c_t,
            const float* __restrict__ hebb,
            const float* __restrict__ alpha,
            const float* __restrict__ mt_w,
            const float* __restrict__ mt_b,
            float* __restrict__ out) {
    __shared__ float red[8][16];         // per-warp column partials
    __shared__ float gsm[NSPLIT][4][16]; // gate partials [sp][gate][k]
    __shared__ float a_s[16];            // m_t[k] * g_t[k]

    const int b  = blockIdx.y;
    const int k0 = blockIdx.x * 16;
    const int t  = threadIdx.x;        // 256
    const int c4 = t & 3;              // float4 column group
    const int r0 = t >> 2;             // base row 0..63
    const int lane = t & 31;
    const int wid  = t >> 5;

    const float* hebb_b = hebb + (size_t)b * HEBB_PER_B + k0 + c4 * 4;
    const float* hrow   = h_t + b * 512;

    // --- front: all global loads issued before any dependency stall ---
    float4 v[8];
    float hr[8];
    #pragma unroll
    for (int j = 0; j < 8; j++)
        v[j] = __ldcs((const float4*)(hebb_b + (size_t)(r0 + j * 64) * 512));
    #pragma unroll
    for (int j = 0; j < 8; j++)
        hr[j] = __ldg(hrow + r0 + j * 64);
    if (t < 16 * NSPLIT) {
        const int ki = t & 15;
        const int sp = t >> 4;
        const float* gb = g_part + (size_t)sp * BB * G4 + b * 2048 + k0 + ki;
        gsm[sp][0][ki] = gb[0];
        gsm[sp][1][ki] = gb[512];
        gsm[sp][2][ki] = gb[1024];
        gsm[sp][3][ki] = gb[1536];
    }

    // --- reduction: acc over this thread's 8 rows ---
    float a0 = 0.f, a1 = 0.f, a2 = 0.f, a3 = 0.f;
    #pragma unroll
    for (int j = 0; j < 8; j++) {
        a0 += hr[j] * v[j].x;
        a1 += hr[j] * v[j].y;
        a2 += hr[j] * v[j].z;
        a3 += hr[j] * v[j].w;
    }
    #pragma unroll
    for (int o = 16; o >= 4; o >>= 1) {
        a0 += __shfl_down_sync(0xffffffff, a0, o);
        a1 += __shfl_down_sync(0xffffffff, a1, o);
        a2 += __shfl_down_sync(0xffffffff, a2, o);
        a3 += __shfl_down_sync(0xffffffff, a3, o);
    }
    if (lane < 4) {
        red[wid][lane * 4 + 0] = a0;
        red[wid][lane * 4 + 1] = a1;
        red[wid][lane * 4 + 2] = a2;
        red[wid][lane * 4 + 3] = a3;
    }
    __syncthreads();

    // --- epilogue for the 16 owned k's (ALU + SMEM only) ---
    if (t < 16) {
        const int k = k0 + t;
        float s = red[0][t] + red[1][t] + red[2][t] + red[3][t]
                + red[4][t] + red[5][t] + red[6][t] + red[7][t];
        float ghebb = alpha[k] * s;

        float zi = 0.f, zf = 0.f, zg = 0.f, zo = 0.f;
        #pragma unroll
        for (int sp = 0; sp < NSPLIT; sp++) {
            zi += gsm[sp][0][t];
            zf += gsm[sp][1][t];
            zg += gsm[sp][2][t];
            zo += gsm[sp][3][t];
        }

        float gt = tanhf(zg + ghebb);
        float it = sigmoidf_(zi);
        float ft = sigmoidf_(zf);
        float ot = sigmoidf_(zo);

        float cn = ft * c_t[b * 512 + k] + it * gt;
        float hn = ot * tanhf(cn);

        out[b * 512 + k]           = hn;     // h_new
        out[BB * HS + b * 512 + k] = cn;     // c_new

        float mt = g_mscalar[b] * mt_w[k] + mt_b[k];
        a_s[t] = mt * gt;
    }
    __syncthreads();

    // --- store: update regs + write hebb_new (streaming stores) ---
    {
        float* outh = out + 2 * BB * HS + (size_t)b * HEBB_PER_B + k0 + c4 * 4;
        float4 av = *(const float4*)&a_s[c4 * 4];
        #pragma unroll
        for (int j = 0; j < 8; j++) {
            int i = r0 + j * 64;
            float hj = hr[j];
            float4 o;
            o.x = fminf(fmaxf(v[j].x + hj * av.x, -2.0f), 2.0f);
            o.y = fminf(fmaxf(v[j].y + hj * av.y, -2.0f), 2.0f);
            o.z = fminf(fmaxf(v[j].z + hj * av.z, -2.0f), 2.0f);
            o.w = fminf(fmaxf(v[j].w + hj * av.w, -2.0f), 2.0f);
            __stcs((float4*)(outh + (size_t)i * 512), o);
        }
    }
}

// ---------------------------------------------------------------------------
extern "C" void kernel_launch(void* const* d_in, const int* in_sizes, int n_in,
                              void* d_out, int out_size) {
    const float* x     = (const float*)d_in[0];
    const float* h     = (const float*)d_in[1];
    const float* c     = (const float*)d_in[2];
    const float* hebb  = (const float*)d_in[3];
    const float* W     = (const float*)d_in[4];
    const float* U     = (const float*)d_in[5];
    const float* bias  = (const float*)d_in[6];
    const float* alpha = (const float*)d_in[7];
    const float* nm_w  = (const float*)d_in[8];
    const float* nm_b  = (const float*)d_in[9];
    const float* mt_w  = (const float*)d_in[10];
    const float* mt_b  = (const float*)d_in[11];
    float* out = (float*)d_out;

    (void)in_sizes; (void)n_in; (void)out_size;

    gemm_gates_kernel<<<dim3(32, 4, NSPLIT), 256>>>(x, h, W, U, bias);
    mscalar_kernel<<<256, 128>>>(h, nm_w, nm_b);
    hebb_kernel<<<dim3(32, 256), 256>>>(h, c, hebb, alpha, mt_w, mt_b, out);
}